// round 3
// baseline (speedup 1.0000x reference)
#include <cuda_runtime.h>

// CausalConv1d (depthwise, K=4) + SiLU
// x: (B=4, S=8192, D=2048) fp32, w: (D, 1, 4) fp32, out: (B, S, D) fp32
// y[b,s,d] = silu( sum_{k=0..3} x[b, s-3+k, d] * w[d,0,k] )   (causal left zero-pad)
//
// Persistent sliding-window: each thread produces 64 consecutive s-positions
// (8 chunks of 8) for one float4 channel group, carrying the 3-row halo in
// registers between chunks (read amplification 67/64 ~= 1.05).

constexpr int B_ = 4;
constexpr int S_ = 8192;
constexpr int D_ = 2048;
constexpr int D4 = D_ / 4;        // 512 float4 lanes along channel dim
constexpr int TC = 8;             // s-positions per chunk
constexpr int NCHUNK = 8;         // chunks per thread -> 64 s-positions/thread
constexpr int THREADS = 128;

// silu(v) = h + h*tanh(h), h = v/2.  One MUFU op.
__device__ __forceinline__ float silu_f(float v) {
    float h = 0.5f * v;
    float t;
    asm("tanh.approx.f32 %0, %1;" : "=f"(t) : "f"(h));
    return fmaf(h, t, h);
}

__global__ __launch_bounds__(THREADS, 7)
void causal_conv1d_silu_kernel(const float4* __restrict__ x,
                               const float4* __restrict__ w4,   // [D] float4: 4 taps / channel
                               float4* __restrict__ y)
{
    const int d4 = blockIdx.x * THREADS + threadIdx.x;   // float4 channel group
    const int s0 = blockIdx.y * (TC * NCHUNK);           // first s this thread produces
    const int b  = blockIdx.z;

    // Taps: w4[c] = (k0,k1,k2,k3) of channel c.
    const int c0 = d4 * 4;
    const float4 wA = __ldg(&w4[c0 + 0]);
    const float4 wB = __ldg(&w4[c0 + 1]);
    const float4 wC = __ldg(&w4[c0 + 2]);
    const float4 wD = __ldg(&w4[c0 + 3]);

    int base = (b * S_ + s0) * D4 + d4;  // float4 index of (b, s0+8*c, d4); advances per chunk

    // ---- Prologue: fill window r[0..10] = rows s0-3 .. s0+7 ----
    float4 r[TC + 3];
    if (blockIdx.y != 0) {
        r[0] = x[base - 3 * D4];
        r[1] = x[base - 2 * D4];
        r[2] = x[base - 1 * D4];
    } else {
        const float4 z = make_float4(0.f, 0.f, 0.f, 0.f);
        r[0] = z; r[1] = z; r[2] = z;
    }
#pragma unroll
    for (int t = 0; t < TC; ++t)
        r[t + 3] = x[base + t * D4];

#pragma unroll
    for (int c = 0; c < NCHUNK; ++c) {
#pragma unroll
        for (int t = 0; t < TC; ++t) {
            float4 o;
            o.x = fmaf(r[t].x, wA.x, fmaf(r[t+1].x, wA.y, fmaf(r[t+2].x, wA.z, r[t+3].x * wA.w)));
            o.y = fmaf(r[t].y, wB.x, fmaf(r[t+1].y, wB.y, fmaf(r[t+2].y, wB.z, r[t+3].y * wB.w)));
            o.z = fmaf(r[t].z, wC.x, fmaf(r[t+1].z, wC.y, fmaf(r[t+2].z, wC.z, r[t+3].z * wC.w)));
            o.w = fmaf(r[t].w, wD.x, fmaf(r[t+1].w, wD.y, fmaf(r[t+2].w, wD.z, r[t+3].w * wD.w)));

            o.x = silu_f(o.x);
            o.y = silu_f(o.y);
            o.z = silu_f(o.z);
            o.w = silu_f(o.w);

            // Streaming store: output never re-read — keep L2 for x.
            __stcs(&y[base + t * D4], o);
        }

        if (c + 1 < NCHUNK) {
            // Shift halo, advance, load next 8 rows (issued back-to-back -> high MLP;
            // the next chunk's FMAs consume them in load order, pipelining naturally).
            r[0] = r[TC + 0];
            r[1] = r[TC + 1];
            r[2] = r[TC + 2];
            base += TC * D4;
#pragma unroll
            for (int t = 0; t < TC; ++t)
                r[t + 3] = x[base + t * D4];
        }
    }
}

extern "C" void kernel_launch(void* const* d_in, const int* in_sizes, int n_in,
                              void* d_out, int out_size)
{
    const float4* x  = (const float4*)d_in[0];
    const float4* w4 = (const float4*)d_in[1];
    float4* y = (float4*)d_out;

    dim3 block(THREADS, 1, 1);
    dim3 grid(D4 / THREADS, S_ / (TC * NCHUNK), B_);   // (4, 128, 4) = 2048 CTAs
    causal_conv1d_silu_kernel<<<grid, block>>>(x, w4, y);
}

// round 4
// speedup vs baseline: 1.0670x; 1.0670x over previous
#include <cuda_runtime.h>

// CausalConv1d (depthwise, K=4) + SiLU
// x: (B=4, S=8192, D=2048) fp32, w: (D, 1, 4) fp32, out: (B, S, D) fp32
// y[b,s,d] = silu( sum_{k=0..3} x[b, s-3+k, d] * w[d,0,k] )   (causal left zero-pad)
//
// One-shot tile per thread: 19 front-batched LDG.128 -> 16 outputs.
// (R2's chunked sliding window serialized loads behind stores and regressed;
//  this keeps R1's proven front-batched shape with lower halo amplification.)

constexpr int B_ = 4;
constexpr int S_ = 8192;
constexpr int D_ = 2048;
constexpr int D4 = D_ / 4;      // 512 float4 lanes along channel dim
constexpr int T_ = 16;          // s-positions per thread
constexpr int THREADS = 128;

// silu(v) = h + h*tanh(h), h = v/2.  One MUFU op.
__device__ __forceinline__ float silu_f(float v) {
    float h = 0.5f * v;
    float t;
    asm("tanh.approx.f32 %0, %1;" : "=f"(t) : "f"(h));
    return fmaf(h, t, h);
}

__global__ __launch_bounds__(THREADS, 5)
void causal_conv1d_silu_kernel(const float4* __restrict__ x,
                               const float4* __restrict__ w4,   // [D] float4: 4 taps / channel
                               float4* __restrict__ y)
{
    const int d4 = blockIdx.x * THREADS + threadIdx.x;   // float4 channel group
    const int s0 = blockIdx.y * T_;
    const int b  = blockIdx.z;

    const int base = (b * S_ + s0) * D4 + d4;            // float4 index of (b, s0, d4)

    // ---- Front-batched loads: 19 independent LDG.128 ----
    float4 r[T_ + 3];
    if (blockIdx.y != 0) {
        r[0] = x[base - 3 * D4];
        r[1] = x[base - 2 * D4];
        r[2] = x[base - 1 * D4];
    } else {
        const float4 z = make_float4(0.f, 0.f, 0.f, 0.f);
        r[0] = z; r[1] = z; r[2] = z;
    }
#pragma unroll
    for (int t = 0; t < T_; ++t)
        r[t + 3] = x[base + t * D4];

    // Taps: w4[c] = (k0,k1,k2,k3) of channel c.
    const int c0 = d4 * 4;
    const float4 wA = __ldg(&w4[c0 + 0]);
    const float4 wB = __ldg(&w4[c0 + 1]);
    const float4 wC = __ldg(&w4[c0 + 2]);
    const float4 wD = __ldg(&w4[c0 + 3]);

#pragma unroll
    for (int t = 0; t < T_; ++t) {
        float4 o;
        o.x = fmaf(r[t].x, wA.x, fmaf(r[t+1].x, wA.y, fmaf(r[t+2].x, wA.z, r[t+3].x * wA.w)));
        o.y = fmaf(r[t].y, wB.x, fmaf(r[t+1].y, wB.y, fmaf(r[t+2].y, wB.z, r[t+3].y * wB.w)));
        o.z = fmaf(r[t].z, wC.x, fmaf(r[t+1].z, wC.y, fmaf(r[t+2].z, wC.z, r[t+3].z * wC.w)));
        o.w = fmaf(r[t].w, wD.x, fmaf(r[t+1].w, wD.y, fmaf(r[t+2].w, wD.z, r[t+3].w * wD.w)));

        o.x = silu_f(o.x);
        o.y = silu_f(o.y);
        o.z = silu_f(o.z);
        o.w = silu_f(o.w);

        // Streaming store: output never re-read — keep L2 for x halos.
        __stcs(&y[base + t * D4], o);
    }
}

extern "C" void kernel_launch(void* const* d_in, const int* in_sizes, int n_in,
                              void* d_out, int out_size)
{
    const float4* x  = (const float4*)d_in[0];
    const float4* w4 = (const float4*)d_in[1];
    float4* y = (float4*)d_out;

    dim3 block(THREADS, 1, 1);
    dim3 grid(D4 / THREADS, S_ / T_, B_);   // (4, 512, 4) = 8192 CTAs
    causal_conv1d_silu_kernel<<<grid, block>>>(x, w4, y);
}

// round 5
// speedup vs baseline: 1.0846x; 1.0165x over previous
#include <cuda_runtime.h>

// CausalConv1d (depthwise, K=4) + SiLU
// x: (B=4, S=8192, D=2048) fp32, w: (D, 1, 4) fp32, out: (B, S, D) fp32
// y[b,s,d] = silu( sum_{k=0..3} x[b, s-3+k, d] * w[d,0,k] )   (causal left zero-pad)
//
// Shape from R1 (best): T=8 outputs/thread, 11 front-batched LDG.128, 7 CTAs/SM.
// R4 delta: x reads use evict-first (__ldcs) so L2 capacity favors dirty output
// lines (write buffering) and halo rows instead of dead streaming read data.

constexpr int B_ = 4;
constexpr int S_ = 8192;
constexpr int D_ = 2048;
constexpr int D4 = D_ / 4;      // 512 float4 lanes along channel dim
constexpr int T_ = 8;           // s-positions per thread
constexpr int THREADS = 128;

// silu(v) = h + h*tanh(h), h = v/2.  One MUFU op.
__device__ __forceinline__ float silu_f(float v) {
    float h = 0.5f * v;
    float t;
    asm("tanh.approx.f32 %0, %1;" : "=f"(t) : "f"(h));
    return fmaf(h, t, h);
}

__global__ __launch_bounds__(THREADS, 7)
void causal_conv1d_silu_kernel(const float4* __restrict__ x,
                               const float4* __restrict__ w4,   // [D] float4: 4 taps / channel
                               float4* __restrict__ y)
{
    const int d4 = blockIdx.x * THREADS + threadIdx.x;   // float4 channel group
    const int s0 = blockIdx.y * T_;
    const int b  = blockIdx.z;

    const int base = (b * S_ + s0) * D4 + d4;            // float4 index of (b, s0, d4)

    // ---- Front-batched loads: 11 independent LDG.128, evict-first ----
    float4 r[T_ + 3];
    if (blockIdx.y != 0) {
        r[0] = __ldcs(&x[base - 3 * D4]);
        r[1] = __ldcs(&x[base - 2 * D4]);
        r[2] = __ldcs(&x[base - 1 * D4]);
    } else {
        const float4 z = make_float4(0.f, 0.f, 0.f, 0.f);
        r[0] = z; r[1] = z; r[2] = z;
    }
#pragma unroll
    for (int t = 0; t < T_; ++t)
        r[t + 3] = __ldcs(&x[base + t * D4]);

    // Taps: w4[c] = (k0,k1,k2,k3) of channel c.  (L2-resident, default policy.)
    const int c0 = d4 * 4;
    const float4 wA = __ldg(&w4[c0 + 0]);
    const float4 wB = __ldg(&w4[c0 + 1]);
    const float4 wC = __ldg(&w4[c0 + 2]);
    const float4 wD = __ldg(&w4[c0 + 3]);

#pragma unroll
    for (int t = 0; t < T_; ++t) {
        float4 o;
        o.x = fmaf(r[t].x, wA.x, fmaf(r[t+1].x, wA.y, fmaf(r[t+2].x, wA.z, r[t+3].x * wA.w)));
        o.y = fmaf(r[t].y, wB.x, fmaf(r[t+1].y, wB.y, fmaf(r[t+2].y, wB.z, r[t+3].y * wB.w)));
        o.z = fmaf(r[t].z, wC.x, fmaf(r[t+1].z, wC.y, fmaf(r[t+2].z, wC.z, r[t+3].z * wC.w)));
        o.w = fmaf(r[t].w, wD.x, fmaf(r[t+1].w, wD.y, fmaf(r[t+2].w, wD.z, r[t+3].w * wD.w)));

        o.x = silu_f(o.x);
        o.y = silu_f(o.y);
        o.z = silu_f(o.z);
        o.w = silu_f(o.w);

        // Streaming store: output never re-read.
        __stcs(&y[base + t * D4], o);
    }
}

extern "C" void kernel_launch(void* const* d_in, const int* in_sizes, int n_in,
                              void* d_out, int out_size)
{
    const float4* x  = (const float4*)d_in[0];
    const float4* w4 = (const float4*)d_in[1];
    float4* y = (float4*)d_out;

    dim3 block(THREADS, 1, 1);
    dim3 grid(D4 / THREADS, S_ / T_, B_);   // (4, 1024, 4) = 16384 CTAs
    causal_conv1d_silu_kernel<<<grid, block>>>(x, w4, y);
}